// round 9
// baseline (speedup 1.0000x reference)
#include <cuda_runtime.h>
#include <cuda_fp16.h>

#define HEADS 8
#define HEAD_DIM 32
#define BATCH 16
#define CDIM 256
#define NTOK 1024                 // 32*32
#define DIMQK (HEADS*HEAD_DIM)    // 256
#define RELW 3969                 // (2*32-1)^2
#define SCALE 0.17677669529663689f

typedef unsigned int u32;

// ---- fp16 mma helpers -----------------------------------------------------
__device__ __forceinline__ u32 pkh2(float a, float b) {
    __half2 h = __floats2half2_rn(a, b);
    return *(u32*)&h;
}
__device__ __forceinline__ uint2 cvt4h(float4 v) {
    return make_uint2(pkh2(v.x, v.y), pkh2(v.z, v.w));
}
// D += A(16x16,row) * B(16x8,col).  c0:(g,2t) c1:(g,2t+1) c2:(g+8,2t) c3:(g+8,2t+1)
__device__ __forceinline__ void mma16(float* c,
                                      u32 a0, u32 a1, u32 a2, u32 a3,
                                      u32 b0, u32 b1) {
    asm("mma.sync.aligned.m16n8k16.row.col.f32.f16.f16.f32 "
        "{%0,%1,%2,%3}, {%4,%5,%6,%7}, {%8,%9}, {%0,%1,%2,%3};"
        : "+f"(c[0]), "+f"(c[1]), "+f"(c[2]), "+f"(c[3])
        : "r"(a0), "r"(a1), "r"(a2), "r"(a3), "r"(b0), "r"(b1));
}
__device__ __forceinline__ u32 sptr(const void* p) {
    return (u32)__cvta_generic_to_shared(p);
}
__device__ __forceinline__ void ldsm_x4(u32& a, u32& b, u32& c, u32& d, u32 addr) {
    asm volatile("ldmatrix.sync.aligned.m8n8.x4.shared.b16 {%0,%1,%2,%3}, [%4];"
                 : "=r"(a), "=r"(b), "=r"(c), "=r"(d) : "r"(addr));
}
__device__ __forceinline__ void ldsm_x2(u32& a, u32& b, u32 addr) {
    asm volatile("ldmatrix.sync.aligned.m8n8.x2.shared.b16 {%0,%1}, [%2];"
                 : "=r"(a), "=r"(b) : "r"(addr));
}
__device__ __forceinline__ void ldsm_x2_t(u32& a, u32& b, u32 addr) {
    asm volatile("ldmatrix.sync.aligned.m8n8.x2.trans.shared.b16 {%0,%1}, [%2];"
                 : "=r"(a), "=r"(b) : "r"(addr));
}

// Scratch (device globals: allocation-free contract) — fp16 intermediates
__device__ __half g_q[BATCH*HEADS*NTOK*HEAD_DIM];
__device__ __half g_k[BATCH*HEADS*NTOK*HEAD_DIM];
__device__ __half g_v[BATCH*HEADS*NTOK*HEAD_DIM];
__device__ __half g_ao[BATCH*NTOK*DIMQK];   // attention output, [b, n, dim]

// ---------------------------------------------------------------------------
// Kernel 1: fused QKV projection via fp16 mma, double-buffered smem.
// C[p, dim] = X^T[p,c] @ W^T[c,dim].  Xs transposed [p][c], Ws natural [dim][c].
// 128x128 tile, 256 thr = 8 warps (2x4), k-chunk 16, 1 sync/iter.
// ---------------------------------------------------------------------------
__global__ __launch_bounds__(256, 2) void qkv_kernel(const float* __restrict__ x,
                                                     const float* __restrict__ Wq,
                                                     const float* __restrict__ Wk,
                                                     const float* __restrict__ Wv) {
    __shared__ __align__(16) __half Xs[2][128][24];   // [p][c]; 48B rows: 3r%8 inj.
    __shared__ __align__(16) __half Ws[2][128][24];   // [dim][c]

    const int tid = threadIdx.x;
    const int lane = tid & 31, wid = tid >> 5;
    const int wm = (wid & 1) * 64;     // p offset
    const int wn = (wid >> 1) * 32;    // dim offset

    const int arow = lane & 15, ahalf = (lane >> 4) * 8;
    const int brow = lane & 7,  bhalf = ((lane >> 3) & 1) * 8;

    const int p0 = blockIdx.x * 128;
    const int d0 = blockIdx.y * 128;
    const int which = blockIdx.z % 3;
    const int bb    = blockIdx.z / 3;

    const float* W = (which == 0) ? Wq : (which == 1) ? Wk : Wv;
    __half* outp = (which == 0) ? g_q : (which == 1) ? g_k : g_v;
    const float* xb = x + (size_t)bb * CDIM * NTOK;

    const int xp  = tid & 127;
    const int xq0 = tid >> 7;          // 0 or 1
    const int wd0 = tid >> 2, wc0 = (tid & 3) * 4;

    float acc[4][4][4] = {};   // [mt][nt][c0..c3]

    // prefetch + stage chunk 0
    float xv[2][4];
    float4 wa, wb;
    #pragma unroll
    for (int qi = 0; qi < 2; qi++) {
        const int cq = xq0 + qi * 2;
        #pragma unroll
        for (int j = 0; j < 4; j++)
            xv[qi][j] = xb[(size_t)(cq * 4 + j) * NTOK + p0 + xp];
    }
    wa = *(const float4*)&W[(size_t)(d0 + wd0) * CDIM + wc0];
    wb = *(const float4*)&W[(size_t)(d0 + wd0 + 64) * CDIM + wc0];
    #pragma unroll
    for (int qi = 0; qi < 2; qi++) {
        const int cq = xq0 + qi * 2;
        *(uint2*)&Xs[0][xp][cq * 4] = make_uint2(pkh2(xv[qi][0], xv[qi][1]),
                                                 pkh2(xv[qi][2], xv[qi][3]));
    }
    *(uint2*)&Ws[0][wd0][wc0]      = cvt4h(wa);
    *(uint2*)&Ws[0][wd0 + 64][wc0] = cvt4h(wb);
    __syncthreads();

    for (int it = 0; it < CDIM / 16; it++) {
        const int buf = it & 1;
        const int c0n = (it + 1) * 16;
        if (c0n < CDIM) {
            #pragma unroll
            for (int qi = 0; qi < 2; qi++) {
                const int cq = xq0 + qi * 2;
                #pragma unroll
                for (int j = 0; j < 4; j++)
                    xv[qi][j] = xb[(size_t)(c0n + cq * 4 + j) * NTOK + p0 + xp];
            }
            wa = *(const float4*)&W[(size_t)(d0 + wd0) * CDIM + c0n + wc0];
            wb = *(const float4*)&W[(size_t)(d0 + wd0 + 64) * CDIM + c0n + wc0];
        }

        const u32 xs_base = sptr(&Xs[buf][0][0]);
        const u32 ws_base = sptr(&Ws[buf][0][0]);
        u32 af[4][4];
        #pragma unroll
        for (int mt = 0; mt < 4; mt++) {
            const u32 addr = xs_base + ((wm + mt * 16 + arow) * 24 + ahalf) * 2;
            ldsm_x4(af[mt][0], af[mt][1], af[mt][2], af[mt][3], addr);
        }
        #pragma unroll
        for (int nt = 0; nt < 4; nt++) {
            u32 b0, b1;
            const u32 addr = ws_base + ((wn + nt * 8 + brow) * 24 + bhalf) * 2;
            ldsm_x2(b0, b1, addr);
            #pragma unroll
            for (int mt = 0; mt < 4; mt++)
                mma16(acc[mt][nt], af[mt][0], af[mt][1], af[mt][2], af[mt][3], b0, b1);
        }

        if (c0n < CDIM) {
            const int nb = buf ^ 1;
            #pragma unroll
            for (int qi = 0; qi < 2; qi++) {
                const int cq = xq0 + qi * 2;
                *(uint2*)&Xs[nb][xp][cq * 4] = make_uint2(pkh2(xv[qi][0], xv[qi][1]),
                                                          pkh2(xv[qi][2], xv[qi][3]));
            }
            *(uint2*)&Ws[nb][wd0][wc0]      = cvt4h(wa);
            *(uint2*)&Ws[nb][wd0 + 64][wc0] = cvt4h(wb);
            __syncthreads();
        }
    }

    const int g = lane >> 2, t = lane & 3;
    const float sc = (which == 1) ? SCALE : 1.0f;
    #pragma unroll
    for (int mt = 0; mt < 4; mt++) {
        const int pr0 = p0 + wm + mt * 16 + g;
        #pragma unroll
        for (int nt = 0; nt < 4; nt++) {
            const int dim = d0 + wn + nt * 8 + 2 * t;
            const int h = dim >> 5, dd = dim & 31;
            __half* base0 = &outp[(((size_t)bb * HEADS + h) * NTOK + pr0) * HEAD_DIM + dd];
            __half* base1 = &outp[(((size_t)bb * HEADS + h) * NTOK + pr0 + 8) * HEAD_DIM + dd];
            *(u32*)base0 = pkh2(acc[mt][nt][0] * sc, acc[mt][nt][1] * sc);
            *(u32*)base1 = pkh2(acc[mt][nt][2] * sc, acc[mt][nt][3] * sc);
        }
    }
}

// ---------------------------------------------------------------------------
// Kernel 2: attention via fp16 mma, double-buffered K/V, fp16 staging copies.
// Block = (b, h, 128-q), 256 thr.  Warp owns 16 q rows.  32-key tiles.
// ---------------------------------------------------------------------------
__global__ __launch_bounds__(256, 2) void attn_kernel(const float* __restrict__ rel_bias,
                                                      const int*   __restrict__ rel_idx) {
    __shared__ __align__(16) __half Qs[128][40];      // [q][d]; 80B rows: 5r%8 inj.
    __shared__ __align__(16) __half Ks[2][32][40];    // [key][d]
    __shared__ __align__(16) __half Vs[2][32][40];    // [key][d] (trans-ldsm for PV)
    __shared__ __align__(16) __half Ps[128][40];      // [q][key]

    const int tid = threadIdx.x;
    const int lane = tid & 31, wid = tid >> 5;
    const int g = lane >> 2, t = lane & 3;
    const int m0 = wid * 16;

    const int arow = lane & 15, ahalf = (lane >> 4) * 8;
    const int brow = lane & 7,  bhalf = ((lane >> 3) & 1) * 8;

    const int q0 = blockIdx.x * 128;
    const int h  = blockIdx.y;
    const int bb = blockIdx.z;

    const size_t ho = ((size_t)bb * HEADS + h) * NTOK * HEAD_DIM;
    const __half* qb = g_q + ho;
    const __half* kb = g_k + ho;
    const __half* vb = g_v + ho;
    const float* bias_h = rel_bias + (size_t)h * RELW;

    const u32 qs_base = sptr(&Qs[0][0]);
    const u32 ps_base = sptr(&Ps[0][0]);

    // stage Q tile (raw fp16 copy, uint4 = 8 halfs)
    #pragma unroll
    for (int j = 0; j < 2; j++) {
        int id = tid + 256 * j;
        int qr = id >> 2, dq = (id & 3) * 8;
        *(uint4*)&Qs[qr][dq] = *(const uint4*)&qb[(size_t)(q0 + qr) * HEAD_DIM + dq];
    }

    // K/V staging (uint2 = 4 halfs per thread per array)
    const int skey = tid >> 3, sdq = (tid & 7) * 4;
    uint2 kf = *(const uint2*)&kb[(size_t)skey * HEAD_DIM + sdq];
    uint2 vf = *(const uint2*)&vb[(size_t)skey * HEAD_DIM + sdq];
    *(uint2*)&Ks[0][skey][sdq] = kf;
    *(uint2*)&Vs[0][skey][sdq] = vf;
    __syncthreads();

    // persistent Q A-frags: 2 k-steps over d=32
    u32 qa[2][4];
    #pragma unroll
    for (int ks = 0; ks < 2; ks++) {
        const u32 addr = qs_base + ((m0 + arow) * 40 + ks * 16 + ahalf) * 2;
        ldsm_x4(qa[ks][0], qa[ks][1], qa[ks][2], qa[ks][3], addr);
    }

    float out[4][4] = {};     // [nt(d)][c0..c3]
    float l0 = 0.0f, l1 = 0.0f;

    const int qr0 = q0 + m0 + g;
    const int qr1 = qr0 + 8;

    for (int kt = 0; kt < NTOK / 32; kt++) {
        const int buf = kt & 1;
        const int kbase = kt * 32;
        if (kt + 1 < NTOK / 32) {
            kf = *(const uint2*)&kb[(size_t)(kbase + 32 + skey) * HEAD_DIM + sdq];
            vf = *(const uint2*)&vb[(size_t)(kbase + 32 + skey) * HEAD_DIM + sdq];
        }

        const u32 ks_base = sptr(&Ks[buf][0][0]);
        const u32 vs_base = sptr(&Vs[buf][0][0]);

        // S = Q K^T : 4 n-tiles (8 keys) x 2 k-steps (d)
        float s[4][4] = {};
        #pragma unroll
        for (int ks = 0; ks < 2; ks++) {
            #pragma unroll
            for (int nt = 0; nt < 4; nt++) {
                u32 b0, b1;
                const u32 addr = ks_base + ((nt * 8 + brow) * 40 + ks * 16 + bhalf) * 2;
                ldsm_x2(b0, b1, addr);
                mma16(s[nt], qa[ks][0], qa[ks][1], qa[ks][2], qa[ks][3], b0, b1);
            }
        }

        // bias + exp; stage P (fp16); accumulate normalizer
        #pragma unroll
        for (int nt = 0; nt < 4; nt++) {
            const int keyc = kbase + nt * 8 + 2 * t;
            int2 r0 = *(const int2*)&rel_idx[(size_t)qr0 * NTOK + keyc];
            int2 r1 = *(const int2*)&rel_idx[(size_t)qr1 * NTOK + keyc];
            float p0 = __expf(s[nt][0] + __ldg(&bias_h[r0.x]));
            float p1 = __expf(s[nt][1] + __ldg(&bias_h[r0.y]));
            float p2 = __expf(s[nt][2] + __ldg(&bias_h[r1.x]));
            float p3 = __expf(s[nt][3] + __ldg(&bias_h[r1.y]));
            l0 += p0 + p1;
            l1 += p2 + p3;
            const int col = nt * 8 + 2 * t;
            *(u32*)&Ps[m0 + g][col]     = pkh2(p0, p1);
            *(u32*)&Ps[m0 + g + 8][col] = pkh2(p2, p3);
        }
        __syncwarp();   // Ps produced+consumed within this warp

        // PV: 2 k-steps over 32 keys; B = V^T via trans ldsm
        #pragma unroll
        for (int ks = 0; ks < 2; ks++) {
            u32 a0, a1, a2, a3;
            const u32 pa = ps_base + ((m0 + arow) * 40 + ks * 16 + ahalf) * 2;
            ldsm_x4(a0, a1, a2, a3, pa);
            #pragma unroll
            for (int nt = 0; nt < 4; nt++) {
                u32 b0, b1;
                const u32 va = vs_base + ((ks * 16 + brow + bhalf) * 40 + nt * 8) * 2;
                ldsm_x2_t(b0, b1, va);
                mma16(out[nt], a0, a1, a2, a3, b0, b1);
            }
        }

        if (kt + 1 < NTOK / 32) {
            const int nb = buf ^ 1;
            *(uint2*)&Ks[nb][skey][sdq] = kf;
            *(uint2*)&Vs[nb][skey][sdq] = vf;
            __syncthreads();
        }
    }

    l0 += __shfl_xor_sync(0xFFFFFFFFu, l0, 1);
    l0 += __shfl_xor_sync(0xFFFFFFFFu, l0, 2);
    l1 += __shfl_xor_sync(0xFFFFFFFFu, l1, 1);
    l1 += __shfl_xor_sync(0xFFFFFFFFu, l1, 2);
    const float inv0 = 1.0f / l0;
    const float inv1 = 1.0f / l1;

    #pragma unroll
    for (int nt = 0; nt < 4; nt++) {
        const int dcol = h * HEAD_DIM + nt * 8 + 2 * t;
        *(u32*)&g_ao[((size_t)bb * NTOK + qr0) * DIMQK + dcol] =
            pkh2(out[nt][0] * inv0, out[nt][1] * inv0);
        *(u32*)&g_ao[((size_t)bb * NTOK + qr1) * DIMQK + dcol] =
            pkh2(out[nt][2] * inv1, out[nt][3] * inv1);
    }
}

// ---------------------------------------------------------------------------
// Kernel 3: output projection via fp16 mma, double-buffered smem.
// y[b,c,p] = bo[c] + sum_j Wo[c,j] * ao[b,p,j].  As=[c][j] (cvt), Bs=[p][j] (copy).
// ---------------------------------------------------------------------------
__global__ __launch_bounds__(256, 2) void proj_kernel(const float* __restrict__ Wo,
                                                      const float* __restrict__ bo,
                                                      float* __restrict__ y) {
    __shared__ __align__(16) __half As[2][128][24];   // [c][j]
    __shared__ __align__(16) __half Bs[2][128][24];   // [p][j]

    const int tid = threadIdx.x;
    const int lane = tid & 31, wid = tid >> 5;
    const int g = lane >> 2, t = lane & 3;
    const int wm = (wid & 1) * 64;     // c offset
    const int wn = (wid >> 1) * 32;    // p offset

    const int arow = lane & 15, ahalf = (lane >> 4) * 8;
    const int brow = lane & 7,  bhalf = ((lane >> 3) & 1) * 8;

    const int p0 = blockIdx.x * 128;
    const int c0 = blockIdx.y * 128;
    const int bb = blockIdx.z;

    const __half* ab = g_ao + (size_t)bb * NTOK * DIMQK;

    const int lr0 = tid >> 2, lq = (tid & 3) * 4;

    float acc[4][4][4] = {};

    float4 aa, ab4;
    uint2 ba, bb4;
    aa  = *(const float4*)&Wo[(size_t)(c0 + lr0) * DIMQK + lq];
    ab4 = *(const float4*)&Wo[(size_t)(c0 + lr0 + 64) * DIMQK + lq];
    ba  = *(const uint2*)&ab[(size_t)(p0 + lr0) * DIMQK + lq];
    bb4 = *(const uint2*)&ab[(size_t)(p0 + lr0 + 64) * DIMQK + lq];
    *(uint2*)&As[0][lr0][lq]      = cvt4h(aa);
    *(uint2*)&As[0][lr0 + 64][lq] = cvt4h(ab4);
    *(uint2*)&Bs[0][lr0][lq]      = ba;
    *(uint2*)&Bs[0][lr0 + 64][lq] = bb4;
    __syncthreads();

    for (int it = 0; it < DIMQK / 16; it++) {
        const int buf = it & 1;
        const int j0n = (it + 1) * 16;
        if (j0n < DIMQK) {
            aa  = *(const float4*)&Wo[(size_t)(c0 + lr0) * DIMQK + j0n + lq];
            ab4 = *(const float4*)&Wo[(size_t)(c0 + lr0 + 64) * DIMQK + j0n + lq];
            ba  = *(const uint2*)&ab[(size_t)(p0 + lr0) * DIMQK + j0n + lq];
            bb4 = *(const uint2*)&ab[(size_t)(p0 + lr0 + 64) * DIMQK + j0n + lq];
        }

        const u32 as_base = sptr(&As[buf][0][0]);
        const u32 bs_base = sptr(&Bs[buf][0][0]);
        u32 af[4][4];
        #pragma unroll
        for (int mt = 0; mt < 4; mt++) {
            const u32 addr = as_base + ((wm + mt * 16 + arow) * 24 + ahalf) * 2;
            ldsm_x4(af[mt][0], af[mt][1], af[mt][2], af[mt][3], addr);
        }
        #pragma unroll
        for (int nt = 0; nt < 4; nt++) {
            u32 b0, b1;
            const u32 addr = bs_base + ((wn + nt * 8 + brow) * 24 + bhalf) * 2;
            ldsm_x2(b0, b1, addr);
            #pragma unroll
            for (int mt = 0; mt < 4; mt++)
                mma16(acc[mt][nt], af[mt][0], af[mt][1], af[mt][2], af[mt][3], b0, b1);
        }

        if (j0n < DIMQK) {
            const int nb = buf ^ 1;
            *(uint2*)&As[nb][lr0][lq]      = cvt4h(aa);
            *(uint2*)&As[nb][lr0 + 64][lq] = cvt4h(ab4);
            *(uint2*)&Bs[nb][lr0][lq]      = ba;
            *(uint2*)&Bs[nb][lr0 + 64][lq] = bb4;
            __syncthreads();
        }
    }

    #pragma unroll
    for (int mt = 0; mt < 4; mt++) {
        const int cr0 = c0 + wm + mt * 16 + g;
        const float bias0 = __ldg(&bo[cr0]);
        const float bias1 = __ldg(&bo[cr0 + 8]);
        #pragma unroll
        for (int nt = 0; nt < 4; nt++) {
            const int pc = p0 + wn + nt * 8 + 2 * t;
            *(float2*)&y[((size_t)bb * CDIM + cr0) * NTOK + pc] =
                make_float2(acc[mt][nt][0] + bias0, acc[mt][nt][1] + bias0);
            *(float2*)&y[((size_t)bb * CDIM + cr0 + 8) * NTOK + pc] =
                make_float2(acc[mt][nt][2] + bias1, acc[mt][nt][3] + bias1);
        }
    }
}

// ---------------------------------------------------------------------------
extern "C" void kernel_launch(void* const* d_in, const int* in_sizes, int n_in,
                              void* d_out, int out_size) {
    const float* x        = (const float*)d_in[0];
    const float* Wq       = (const float*)d_in[1];
    const float* Wk       = (const float*)d_in[2];
    const float* Wv       = (const float*)d_in[3];
    const float* Wo       = (const float*)d_in[4];
    const float* bo       = (const float*)d_in[5];
    const float* rel_bias = (const float*)d_in[6];
    const int*   rel_idx  = (const int*)d_in[7];
    float* y = (float*)d_out;

    dim3 g1(NTOK / 128, DIMQK / 128, BATCH * 3);
    qkv_kernel<<<g1, 256>>>(x, Wq, Wk, Wv);

    dim3 g2(NTOK / 128, HEADS, BATCH);
    attn_kernel<<<g2, 256>>>(rel_bias, rel_idx);

    dim3 g3(NTOK / 128, CDIM / 128, BATCH);
    proj_kernel<<<g3, 256>>>(Wo, bo, y);
}

// round 10
// speedup vs baseline: 1.1193x; 1.1193x over previous
#include <cuda_runtime.h>
#include <cuda_fp16.h>

#define HEADS 8
#define HEAD_DIM 32
#define BATCH 16
#define CDIM 256
#define NTOK 1024                 // 32*32
#define DIMQK (HEADS*HEAD_DIM)    // 256
#define RELW 3969                 // (2*32-1)^2
#define SCALE 0.17677669529663689f
#define LOG2E 1.4426950408889634f

typedef unsigned int u32;

// ---- fp16 mma helpers -----------------------------------------------------
__device__ __forceinline__ u32 pkh2(float a, float b) {
    __half2 h = __floats2half2_rn(a, b);
    return *(u32*)&h;
}
__device__ __forceinline__ uint2 cvt4h(float4 v) {
    return make_uint2(pkh2(v.x, v.y), pkh2(v.z, v.w));
}
__device__ __forceinline__ void mma16(float* c,
                                      u32 a0, u32 a1, u32 a2, u32 a3,
                                      u32 b0, u32 b1) {
    asm("mma.sync.aligned.m16n8k16.row.col.f32.f16.f16.f32 "
        "{%0,%1,%2,%3}, {%4,%5,%6,%7}, {%8,%9}, {%0,%1,%2,%3};"
        : "+f"(c[0]), "+f"(c[1]), "+f"(c[2]), "+f"(c[3])
        : "r"(a0), "r"(a1), "r"(a2), "r"(a3), "r"(b0), "r"(b1));
}
__device__ __forceinline__ u32 sptr(const void* p) {
    return (u32)__cvta_generic_to_shared(p);
}
__device__ __forceinline__ void ldsm_x4(u32& a, u32& b, u32& c, u32& d, u32 addr) {
    asm volatile("ldmatrix.sync.aligned.m8n8.x4.shared.b16 {%0,%1,%2,%3}, [%4];"
                 : "=r"(a), "=r"(b), "=r"(c), "=r"(d) : "r"(addr));
}
__device__ __forceinline__ void ldsm_x2(u32& a, u32& b, u32 addr) {
    asm volatile("ldmatrix.sync.aligned.m8n8.x2.shared.b16 {%0,%1}, [%2];"
                 : "=r"(a), "=r"(b) : "r"(addr));
}
__device__ __forceinline__ void ldsm_x2_t(u32& a, u32& b, u32 addr) {
    asm volatile("ldmatrix.sync.aligned.m8n8.x2.trans.shared.b16 {%0,%1}, [%2];"
                 : "=r"(a), "=r"(b) : "r"(addr));
}
__device__ __forceinline__ u32 ex2h2(u32 x) {
    u32 r; asm("ex2.approx.f16x2 %0, %1;" : "=r"(r) : "r"(x)); return r;
}
__device__ __forceinline__ u32 hadd2u(u32 a, u32 b) {
    __half2 r = __hadd2(*(__half2*)&a, *(__half2*)&b);
    return *(u32*)&r;
}
__device__ __forceinline__ void cpa8(u32 saddr, const void* g) {
    asm volatile("cp.async.ca.shared.global [%0], [%1], 8;" :: "r"(saddr), "l"(g));
}
#define CP_COMMIT() asm volatile("cp.async.commit_group;")
#define CP_WAIT(n)  asm volatile("cp.async.wait_group %0;" :: "n"(n))

// Scratch (device globals: allocation-free contract)
__device__ __half g_q[BATCH*HEADS*NTOK*HEAD_DIM];
__device__ __half g_k[BATCH*HEADS*NTOK*HEAD_DIM];   // pre-scaled by SCALE*LOG2E
__device__ __half g_v[BATCH*HEADS*NTOK*HEAD_DIM];
__device__ __half g_ao[BATCH*NTOK*DIMQK];           // attention output, [b, n, dim]
__device__ __half g_bias[HEADS*NTOK*NTOK];          // bias[h][q][k] * LOG2E (fp16)

// ---------------------------------------------------------------------------
// Kernel 0: bias table precompute.  g_bias[h][q][k] = rel_bias[h][rel_idx[q][k]]*LOG2E
// 8.4M halfs; thread does 8 consecutive k.
// ---------------------------------------------------------------------------
__global__ __launch_bounds__(256) void bias_kernel(const float* __restrict__ rel_bias,
                                                   const int*   __restrict__ rel_idx) {
    const int id = blockIdx.x * 256 + threadIdx.x;
    const int base = id * 8;                       // element index in [0, 8*1024*1024)
    const int h = base >> 20;
    const int rem = base & ((1 << 20) - 1);
    const int q = rem >> 10;
    const int k0 = rem & 1023;

    const int* ir = rel_idx + q * NTOK + k0;
    int4 i0 = *(const int4*)ir;
    int4 i1 = *(const int4*)(ir + 4);
    const float* bh = rel_bias + (size_t)h * RELW;

    uint4 o;
    o.x = pkh2(__ldg(&bh[i0.x]) * LOG2E, __ldg(&bh[i0.y]) * LOG2E);
    o.y = pkh2(__ldg(&bh[i0.z]) * LOG2E, __ldg(&bh[i0.w]) * LOG2E);
    o.z = pkh2(__ldg(&bh[i1.x]) * LOG2E, __ldg(&bh[i1.y]) * LOG2E);
    o.w = pkh2(__ldg(&bh[i1.z]) * LOG2E, __ldg(&bh[i1.w]) * LOG2E);
    *(uint4*)&g_bias[base] = o;
}

// ---------------------------------------------------------------------------
// Kernel 1: fused QKV projection via fp16 mma, double-buffered smem.
// K output pre-scaled by SCALE*LOG2E (log2-domain scores for the exp2 path).
// ---------------------------------------------------------------------------
__global__ __launch_bounds__(256, 2) void qkv_kernel(const float* __restrict__ x,
                                                     const float* __restrict__ Wq,
                                                     const float* __restrict__ Wk,
                                                     const float* __restrict__ Wv) {
    __shared__ __align__(16) __half Xs[2][128][24];   // [p][c]; 48B rows: 3r%8 inj.
    __shared__ __align__(16) __half Ws[2][128][24];   // [dim][c]

    const int tid = threadIdx.x;
    const int lane = tid & 31, wid = tid >> 5;
    const int wm = (wid & 1) * 64;     // p offset
    const int wn = (wid >> 1) * 32;    // dim offset

    const int arow = lane & 15, ahalf = (lane >> 4) * 8;
    const int brow = lane & 7,  bhalf = ((lane >> 3) & 1) * 8;

    const int p0 = blockIdx.x * 128;
    const int d0 = blockIdx.y * 128;
    const int which = blockIdx.z % 3;
    const int bb    = blockIdx.z / 3;

    const float* W = (which == 0) ? Wq : (which == 1) ? Wk : Wv;
    __half* outp = (which == 0) ? g_q : (which == 1) ? g_k : g_v;
    const float* xb = x + (size_t)bb * CDIM * NTOK;

    const int xp  = tid & 127;
    const int xq0 = tid >> 7;          // 0 or 1
    const int wd0 = tid >> 2, wc0 = (tid & 3) * 4;

    float acc[4][4][4] = {};   // [mt][nt][c0..c3]

    float xv[2][4];
    float4 wa, wb;
    #pragma unroll
    for (int qi = 0; qi < 2; qi++) {
        const int cq = xq0 + qi * 2;
        #pragma unroll
        for (int j = 0; j < 4; j++)
            xv[qi][j] = xb[(size_t)(cq * 4 + j) * NTOK + p0 + xp];
    }
    wa = *(const float4*)&W[(size_t)(d0 + wd0) * CDIM + wc0];
    wb = *(const float4*)&W[(size_t)(d0 + wd0 + 64) * CDIM + wc0];
    #pragma unroll
    for (int qi = 0; qi < 2; qi++) {
        const int cq = xq0 + qi * 2;
        *(uint2*)&Xs[0][xp][cq * 4] = make_uint2(pkh2(xv[qi][0], xv[qi][1]),
                                                 pkh2(xv[qi][2], xv[qi][3]));
    }
    *(uint2*)&Ws[0][wd0][wc0]      = cvt4h(wa);
    *(uint2*)&Ws[0][wd0 + 64][wc0] = cvt4h(wb);
    __syncthreads();

    for (int it = 0; it < CDIM / 16; it++) {
        const int buf = it & 1;
        const int c0n = (it + 1) * 16;
        if (c0n < CDIM) {
            #pragma unroll
            for (int qi = 0; qi < 2; qi++) {
                const int cq = xq0 + qi * 2;
                #pragma unroll
                for (int j = 0; j < 4; j++)
                    xv[qi][j] = xb[(size_t)(c0n + cq * 4 + j) * NTOK + p0 + xp];
            }
            wa = *(const float4*)&W[(size_t)(d0 + wd0) * CDIM + c0n + wc0];
            wb = *(const float4*)&W[(size_t)(d0 + wd0 + 64) * CDIM + c0n + wc0];
        }

        const u32 xs_base = sptr(&Xs[buf][0][0]);
        const u32 ws_base = sptr(&Ws[buf][0][0]);
        u32 af[4][4];
        #pragma unroll
        for (int mt = 0; mt < 4; mt++) {
            const u32 addr = xs_base + ((wm + mt * 16 + arow) * 24 + ahalf) * 2;
            ldsm_x4(af[mt][0], af[mt][1], af[mt][2], af[mt][3], addr);
        }
        #pragma unroll
        for (int nt = 0; nt < 4; nt++) {
            u32 b0, b1;
            const u32 addr = ws_base + ((wn + nt * 8 + brow) * 24 + bhalf) * 2;
            ldsm_x2(b0, b1, addr);
            #pragma unroll
            for (int mt = 0; mt < 4; mt++)
                mma16(acc[mt][nt], af[mt][0], af[mt][1], af[mt][2], af[mt][3], b0, b1);
        }

        if (c0n < CDIM) {
            const int nb = buf ^ 1;
            #pragma unroll
            for (int qi = 0; qi < 2; qi++) {
                const int cq = xq0 + qi * 2;
                *(uint2*)&Xs[nb][xp][cq * 4] = make_uint2(pkh2(xv[qi][0], xv[qi][1]),
                                                          pkh2(xv[qi][2], xv[qi][3]));
            }
            *(uint2*)&Ws[nb][wd0][wc0]      = cvt4h(wa);
            *(uint2*)&Ws[nb][wd0 + 64][wc0] = cvt4h(wb);
            __syncthreads();
        }
    }

    const int g = lane >> 2, t = lane & 3;
    const float sc = (which == 1) ? SCALE * LOG2E : 1.0f;
    #pragma unroll
    for (int mt = 0; mt < 4; mt++) {
        const int pr0 = p0 + wm + mt * 16 + g;
        #pragma unroll
        for (int nt = 0; nt < 4; nt++) {
            const int dim = d0 + wn + nt * 8 + 2 * t;
            const int h = dim >> 5, dd = dim & 31;
            __half* base0 = &outp[(((size_t)bb * HEADS + h) * NTOK + pr0) * HEAD_DIM + dd];
            __half* base1 = &outp[(((size_t)bb * HEADS + h) * NTOK + pr0 + 8) * HEAD_DIM + dd];
            *(u32*)base0 = pkh2(acc[mt][nt][0] * sc, acc[mt][nt][1] * sc);
            *(u32*)base1 = pkh2(acc[mt][nt][2] * sc, acc[mt][nt][3] * sc);
        }
    }
}

// ---------------------------------------------------------------------------
// Kernel 2: attention.  fp16 mma; scores arrive in log2 domain; exp via
// ex2.approx.f16x2 on (s + bias16); normalizer via ones-column in V (col 32);
// K/V loaded with 3-stage cp.async pipeline (1 sync/iter).
// Block = (b, h, 128-q), 256 thr, 3 CTAs/SM target.
// ---------------------------------------------------------------------------
__global__ __launch_bounds__(256, 3) void attn_kernel() {
    __shared__ __align__(16) __half Qs[128][40];      // [q][d]; 80B rows: 5r%8 inj.
    __shared__ __align__(16) __half Ks[3][32][40];    // [key][d]
    __shared__ __align__(16) __half Vs[3][32][40];    // [key][d 0..31 | ones col 32]
    __shared__ __align__(16) __half Ps[128][40];      // [q][key]

    const int tid = threadIdx.x;
    const int lane = tid & 31, wid = tid >> 5;
    const int g = lane >> 2, t = lane & 3;
    const int m0 = wid * 16;

    const int arow = lane & 15, ahalf = (lane >> 4) * 8;
    const int brow = lane & 7,  bhalf = ((lane >> 3) & 1) * 8;

    const int q0 = blockIdx.x * 128;
    const int h  = blockIdx.y;
    const int bb = blockIdx.z;

    const size_t ho = ((size_t)bb * HEADS + h) * NTOK * HEAD_DIM;
    const __half* qb = g_q + ho;
    const __half* kb = g_k + ho;
    const __half* vb = g_v + ho;

    const u32 qs_base = sptr(&Qs[0][0]);
    const u32 ps_base = sptr(&Ps[0][0]);

    // init V ones columns (cols 32..39) in all 3 stages
    if (tid < 96) {
        const int s = tid >> 5, key = tid & 31;
        u32* r = (u32*)&Vs[s][key][32];
        r[0] = 0x00003C00u;  // {1.0h, 0h}
        r[1] = 0; r[2] = 0; r[3] = 0;
    }

    // stage Q tile (raw fp16 copy)
    #pragma unroll
    for (int j = 0; j < 2; j++) {
        int id = tid + 256 * j;
        int qr = id >> 2, dq = (id & 3) * 8;
        *(uint4*)&Qs[qr][dq] = *(const uint4*)&qb[(size_t)(q0 + qr) * HEAD_DIM + dq];
    }

    // cp.async prologue: tiles 0 and 1
    const int skey = tid >> 3, sdq = (tid & 7) * 4;
    cpa8(sptr(&Ks[0][skey][sdq]), kb + (size_t)skey * HEAD_DIM + sdq);
    cpa8(sptr(&Vs[0][skey][sdq]), vb + (size_t)skey * HEAD_DIM + sdq);
    CP_COMMIT();
    cpa8(sptr(&Ks[1][skey][sdq]), kb + (size_t)(32 + skey) * HEAD_DIM + sdq);
    cpa8(sptr(&Vs[1][skey][sdq]), vb + (size_t)(32 + skey) * HEAD_DIM + sdq);
    CP_COMMIT();

    __syncthreads();   // Qs + ones visible

    u32 qa[2][4];
    #pragma unroll
    for (int ks = 0; ks < 2; ks++) {
        const u32 addr = qs_base + ((m0 + arow) * 40 + ks * 16 + ahalf) * 2;
        ldsm_x4(qa[ks][0], qa[ks][1], qa[ks][2], qa[ks][3], addr);
    }

    float out[5][4] = {};     // nt 0..3: d cols; nt 4: ones column (row sums)

    const int qr0 = q0 + m0 + g;
    const int qr1 = qr0 + 8;
    const __half* brow0 = g_bias + ((size_t)h * NTOK + qr0) * NTOK;
    const __half* brow1 = g_bias + ((size_t)h * NTOK + qr1) * NTOK;

    int sb0 = 0, sb1 = 1, sb2 = 2;     // rotating stage ids

    for (int kt = 0; kt < NTOK / 32; kt++) {
        const int kbase = kt * 32;

        if (kt + 1 < NTOK / 32) { CP_WAIT(1); } else { CP_WAIT(0); }
        __syncthreads();   // tile kt visible to all; all warps past compute(kt-1)

        if (kt + 2 < NTOK / 32) {
            cpa8(sptr(&Ks[sb2][skey][sdq]), kb + (size_t)(kbase + 64 + skey) * HEAD_DIM + sdq);
            cpa8(sptr(&Vs[sb2][skey][sdq]), vb + (size_t)(kbase + 64 + skey) * HEAD_DIM + sdq);
            CP_COMMIT();
        }

        const u32 ks_base = sptr(&Ks[sb0][0][0]);
        const u32 vs_base = sptr(&Vs[sb0][0][0]);

        // S = Q K^T (log2 domain): 4 n-tiles (8 keys) x 2 k-steps (d)
        float s[4][4] = {};
        #pragma unroll
        for (int ks = 0; ks < 2; ks++) {
            #pragma unroll
            for (int nt = 0; nt < 4; nt++) {
                u32 b0, b1;
                const u32 addr = ks_base + ((nt * 8 + brow) * 40 + ks * 16 + bhalf) * 2;
                ldsm_x2(b0, b1, addr);
                mma16(s[nt], qa[ks][0], qa[ks][1], qa[ks][2], qa[ks][3], b0, b1);
            }
        }

        // p = 2^(s + bias16) via ex2.approx.f16x2; stage P
        #pragma unroll
        for (int nt = 0; nt < 4; nt++) {
            const int col = nt * 8 + 2 * t;
            u32 b0 = *(const u32*)&brow0[kbase + col];
            u32 b1 = *(const u32*)&brow1[kbase + col];
            u32 p0 = ex2h2(hadd2u(pkh2(s[nt][0], s[nt][1]), b0));
            u32 p1 = ex2h2(hadd2u(pkh2(s[nt][2], s[nt][3]), b1));
            *(u32*)&Ps[m0 + g][col]     = p0;
            *(u32*)&Ps[m0 + g + 8][col] = p1;
        }
        __syncwarp();   // Ps produced+consumed within this warp

        // PV: 2 k-steps over 32 keys; nt 0..3 = d, nt 4 = ones column (l)
        #pragma unroll
        for (int ks = 0; ks < 2; ks++) {
            u32 a0, a1, a2, a3;
            const u32 pa = ps_base + ((m0 + arow) * 40 + ks * 16 + ahalf) * 2;
            ldsm_x4(a0, a1, a2, a3, pa);
            #pragma unroll
            for (int nt = 0; nt < 5; nt++) {
                u32 b0, b1;
                const u32 va = vs_base + ((ks * 16 + brow + bhalf) * 40 + nt * 8) * 2;
                ldsm_x2_t(b0, b1, va);
                mma16(out[nt], a0, a1, a2, a3, b0, b1);
            }
        }

        // rotate stages
        const int tmp = sb0; sb0 = sb1; sb1 = sb2; sb2 = tmp;
    }

    // normalizers: col 32 sums live in t=0's out[4][0]/out[4][2]
    const int src = lane & 28;   // lane of (g, t=0)
    const float l0 = __shfl_sync(0xFFFFFFFFu, out[4][0], src);
    const float l1 = __shfl_sync(0xFFFFFFFFu, out[4][2], src);
    const float inv0 = 1.0f / l0;
    const float inv1 = 1.0f / l1;

    #pragma unroll
    for (int nt = 0; nt < 4; nt++) {
        const int dcol = h * HEAD_DIM + nt * 8 + 2 * t;
        *(u32*)&g_ao[((size_t)bb * NTOK + qr0) * DIMQK + dcol] =
            pkh2(out[nt][0] * inv0, out[nt][1] * inv0);
        *(u32*)&g_ao[((size_t)bb * NTOK + qr1) * DIMQK + dcol] =
            pkh2(out[nt][2] * inv1, out[nt][3] * inv1);
    }
}

// ---------------------------------------------------------------------------
// Kernel 3: output projection via fp16 mma, double-buffered smem.
// ---------------------------------------------------------------------------
__global__ __launch_bounds__(256, 2) void proj_kernel(const float* __restrict__ Wo,
                                                      const float* __restrict__ bo,
                                                      float* __restrict__ y) {
    __shared__ __align__(16) __half As[2][128][24];   // [c][j]
    __shared__ __align__(16) __half Bs[2][128][24];   // [p][j]

    const int tid = threadIdx.x;
    const int lane = tid & 31, wid = tid >> 5;
    const int g = lane >> 2, t = lane & 3;
    const int wm = (wid & 1) * 64;     // c offset
    const int wn = (wid >> 1) * 32;    // p offset

    const int arow = lane & 15, ahalf = (lane >> 4) * 8;
    const int brow = lane & 7,  bhalf = ((lane >> 3) & 1) * 8;

    const int p0 = blockIdx.x * 128;
    const int c0 = blockIdx.y * 128;
    const int bb = blockIdx.z;

    const __half* ab = g_ao + (size_t)bb * NTOK * DIMQK;

    const int lr0 = tid >> 2, lq = (tid & 3) * 4;

    float acc[4][4][4] = {};

    float4 aa, ab4;
    uint2 ba, bb4;
    aa  = *(const float4*)&Wo[(size_t)(c0 + lr0) * DIMQK + lq];
    ab4 = *(const float4*)&Wo[(size_t)(c0 + lr0 + 64) * DIMQK + lq];
    ba  = *(const uint2*)&ab[(size_t)(p0 + lr0) * DIMQK + lq];
    bb4 = *(const uint2*)&ab[(size_t)(p0 + lr0 + 64) * DIMQK + lq];
    *(uint2*)&As[0][lr0][lq]      = cvt4h(aa);
    *(uint2*)&As[0][lr0 + 64][lq] = cvt4h(ab4);
    *(uint2*)&Bs[0][lr0][lq]      = ba;
    *(uint2*)&Bs[0][lr0 + 64][lq] = bb4;
    __syncthreads();

    for (int it = 0; it < DIMQK / 16; it++) {
        const int buf = it & 1;
        const int j0n = (it + 1) * 16;
        if (j0n < DIMQK) {
            aa  = *(const float4*)&Wo[(size_t)(c0 + lr0) * DIMQK + j0n + lq];
            ab4 = *(const float4*)&Wo[(size_t)(c0 + lr0 + 64) * DIMQK + j0n + lq];
            ba  = *(const uint2*)&ab[(size_t)(p0 + lr0) * DIMQK + j0n + lq];
            bb4 = *(const uint2*)&ab[(size_t)(p0 + lr0 + 64) * DIMQK + j0n + lq];
        }

        const u32 as_base = sptr(&As[buf][0][0]);
        const u32 bs_base = sptr(&Bs[buf][0][0]);
        u32 af[4][4];
        #pragma unroll
        for (int mt = 0; mt < 4; mt++) {
            const u32 addr = as_base + ((wm + mt * 16 + arow) * 24 + ahalf) * 2;
            ldsm_x4(af[mt][0], af[mt][1], af[mt][2], af[mt][3], addr);
        }
        #pragma unroll
        for (int nt = 0; nt < 4; nt++) {
            u32 b0, b1;
            const u32 addr = bs_base + ((wn + nt * 8 + brow) * 24 + bhalf) * 2;
            ldsm_x2(b0, b1, addr);
            #pragma unroll
            for (int mt = 0; mt < 4; mt++)
                mma16(acc[mt][nt], af[mt][0], af[mt][1], af[mt][2], af[mt][3], b0, b1);
        }

        if (j0n < DIMQK) {
            const int nb = buf ^ 1;
            *(uint2*)&As[nb][lr0][lq]      = cvt4h(aa);
            *(uint2*)&As[nb][lr0 + 64][lq] = cvt4h(ab4);
            *(uint2*)&Bs[nb][lr0][lq]      = ba;
            *(uint2*)&Bs[nb][lr0 + 64][lq] = bb4;
            __syncthreads();
        }
    }

    #pragma unroll
    for (int mt = 0; mt < 4; mt++) {
        const int cr0 = c0 + wm + mt * 16 + g;
        const float bias0 = __ldg(&bo[cr0]);
        const float bias1 = __ldg(&bo[cr0 + 8]);
        #pragma unroll
        for (int nt = 0; nt < 4; nt++) {
            const int pc = p0 + wn + nt * 8 + 2 * t;
            *(float2*)&y[((size_t)bb * CDIM + cr0) * NTOK + pc] =
                make_float2(acc[mt][nt][0] + bias0, acc[mt][nt][1] + bias0);
            *(float2*)&y[((size_t)bb * CDIM + cr0 + 8) * NTOK + pc] =
                make_float2(acc[mt][nt][2] + bias1, acc[mt][nt][3] + bias1);
        }
    }
}

// ---------------------------------------------------------------------------
extern "C" void kernel_launch(void* const* d_in, const int* in_sizes, int n_in,
                              void* d_out, int out_size) {
    const float* x        = (const float*)d_in[0];
    const float* Wq       = (const float*)d_in[1];
    const float* Wk       = (const float*)d_in[2];
    const float* Wv       = (const float*)d_in[3];
    const float* Wo       = (const float*)d_in[4];
    const float* bo       = (const float*)d_in[5];
    const float* rel_bias = (const float*)d_in[6];
    const int*   rel_idx  = (const int*)d_in[7];
    float* y = (float*)d_out;

    // bias table: 8*1024*1024 halfs / (256 thr * 8 per thr) = 4096 blocks
    bias_kernel<<<4096, 256>>>(rel_bias, rel_idx);

    dim3 g1(NTOK / 128, DIMQK / 128, BATCH * 3);
    qkv_kernel<<<g1, 256>>>(x, Wq, Wk, Wv);

    dim3 g2(NTOK / 128, HEADS, BATCH);
    attn_kernel<<<g2, 256>>>();

    dim3 g3(NTOK / 128, CDIM / 128, BATCH);
    proj_kernel<<<g3, 256>>>(Wo, bo, y);
}